// round 2
// baseline (speedup 1.0000x reference)
#include <cuda_runtime.h>
#include <cstddef>
#include <math.h>

// ---------------- problem constants ----------------
#define T_ 16
#define N_ 4096
#define C_ 8
#define E_ 65536
#define D_ 256
#define H_ 128
#define G_ 384          // 3*H
#define B_ (T_ * N_)    // 65536

// ---------------- scratch (device globals; no allocation allowed) ----------------
__device__ float g_Hc[B_ * H_];   // comment-GRU hidden, then h_c[t,n,:]
__device__ float g_Gi[B_ * G_];   // gi gate buffer (reused in phase 2 with M=N_)
__device__ float g_Gh[B_ * G_];   // gh gate buffer
__device__ float g_hu[N_ * H_];   // user temporal hidden / h_new carry
__device__ float g_S [N_ * H_];   // self message
__device__ float g_NS[N_ * H_];   // neighbor sum
__device__ float g_NM[N_ * H_];   // neigh_sum @ Wn^T
__device__ float g_deg[N_];       // out-degree (as float)

// ---------------- generic NT SGEMM: C[M,N] = bias[n] + A[M,K] @ W[N,K]^T ----------------
// A row-major with leading dim lda (must be mult of 4, 16B-aligned rows).
// W row-major with leading dim ldw (any stride; scalar loads).
// M % 128 == 0, N % 128 == 0, K % 16 == 0 (guaranteed by the call sites).
#define BM 128
#define BN 128
#define BK 16

__global__ __launch_bounds__(256) void sgemm_nt(
    const float* __restrict__ A, int lda,
    const float* __restrict__ W, int ldw,
    const float* __restrict__ bias,
    float* __restrict__ Cm, int ldc, int K)
{
    __shared__ __align__(16) float As[BK][BM + 4];
    __shared__ __align__(16) float Bs[BK][BN + 4];

    const int tid = threadIdx.x;
    const int tx = tid & 15;        // column group
    const int ty = tid >> 4;        // row group
    const int m0 = blockIdx.y * BM;
    const int n0 = blockIdx.x * BN;

    float acc[8][8];
#pragma unroll
    for (int i = 0; i < 8; i++)
#pragma unroll
        for (int j = 0; j < 8; j++) acc[i][j] = 0.f;

    for (int k0 = 0; k0 < K; k0 += BK) {
        // load A tile (vectorized, lda mult of 4 guarantees alignment)
#pragma unroll
        for (int r = 0; r < 2; r++) {
            int f = tid + r * 256;
            int m = f >> 2;
            int kq = (f & 3) << 2;
            const float4 v = *reinterpret_cast<const float4*>(
                A + (size_t)(m0 + m) * lda + k0 + kq);
            As[kq + 0][m] = v.x; As[kq + 1][m] = v.y;
            As[kq + 2][m] = v.z; As[kq + 3][m] = v.w;
        }
        // load W tile (scalar: ldw may be 129)
#pragma unroll
        for (int r = 0; r < 2; r++) {
            int f = tid + r * 256;
            int n = f >> 2;
            int kq = (f & 3) << 2;
            const float* p = W + (size_t)(n0 + n) * ldw + k0 + kq;
            Bs[kq + 0][n] = p[0]; Bs[kq + 1][n] = p[1];
            Bs[kq + 2][n] = p[2]; Bs[kq + 3][n] = p[3];
        }
        __syncthreads();

#pragma unroll
        for (int k = 0; k < BK; k++) {
            float a[8], b[8];
            *reinterpret_cast<float4*>(&a[0]) = *reinterpret_cast<const float4*>(&As[k][ty * 8]);
            *reinterpret_cast<float4*>(&a[4]) = *reinterpret_cast<const float4*>(&As[k][ty * 8 + 4]);
            *reinterpret_cast<float4*>(&b[0]) = *reinterpret_cast<const float4*>(&Bs[k][tx * 8]);
            *reinterpret_cast<float4*>(&b[4]) = *reinterpret_cast<const float4*>(&Bs[k][tx * 8 + 4]);
#pragma unroll
            for (int i = 0; i < 8; i++)
#pragma unroll
                for (int j = 0; j < 8; j++)
                    acc[i][j] = fmaf(a[i], b[j], acc[i][j]);
        }
        __syncthreads();
    }

    // epilogue
#pragma unroll
    for (int i = 0; i < 8; i++) {
        const int m = m0 + ty * 8 + i;
#pragma unroll
        for (int j = 0; j < 8; j += 4) {
            const int n = n0 + tx * 8 + j;
            float4 o;
            o.x = acc[i][j + 0]; o.y = acc[i][j + 1];
            o.z = acc[i][j + 2]; o.w = acc[i][j + 3];
            if (bias) {
                o.x += bias[n + 0]; o.y += bias[n + 1];
                o.z += bias[n + 2]; o.w += bias[n + 3];
            }
            *reinterpret_cast<float4*>(Cm + (size_t)m * ldc + n) = o;
        }
    }
}

// ---------------- elementwise kernels ----------------
__device__ __forceinline__ float sigmoidf_(float x) { return 1.f / (1.f + expf(-x)); }

__global__ void zero_f(float* __restrict__ p, int n)
{
    int i = blockIdx.x * blockDim.x + threadIdx.x;
    if (i < n) p[i] = 0.f;
}

// h[b,:] <- GRU(h, gi, gh)   (phase 1, in place)
__global__ void gru_update(float* __restrict__ h,
                           const float* __restrict__ Gi,
                           const float* __restrict__ Gh, int Bn)
{
    int idx = blockIdx.x * blockDim.x + threadIdx.x;
    if (idx >= Bn * H_) return;
    int b = idx >> 7, j = idx & 127;
    const float* gi = Gi + (size_t)b * G_;
    const float* gh = Gh + (size_t)b * G_;
    float ir = gi[j], iz = gi[H_ + j], in_ = gi[2 * H_ + j];
    float hr = gh[j], hz = gh[H_ + j], hn = gh[2 * H_ + j];
    float r = sigmoidf_(ir + hr);
    float z = sigmoidf_(iz + hz);
    float nn = tanhf(in_ + r * hn);
    float hp = h[idx];
    h[idx] = (1.f - z) * nn + z * hp;
}

// phase-2 GRU with the prev_y (129th input column) folded in
__global__ void gru_update_u(float* __restrict__ h,
                             const float* __restrict__ Gi,
                             const float* __restrict__ Gh,
                             const float* __restrict__ WihU,   // [384,129]
                             const float* __restrict__ truth, int t)
{
    int idx = blockIdx.x * blockDim.x + threadIdx.x;
    if (idx >= N_ * H_) return;
    int n = idx >> 7, j = idx & 127;
    float py = (t == 0) ? 0.f : truth[(size_t)(t - 1) * N_ + n];
    const float* gi = Gi + (size_t)n * G_;
    const float* gh = Gh + (size_t)n * G_;
    float ir = gi[j]          + py * WihU[(size_t)(j) * 129 + 128];
    float iz = gi[H_ + j]     + py * WihU[(size_t)(H_ + j) * 129 + 128];
    float in_ = gi[2 * H_ + j] + py * WihU[(size_t)(2 * H_ + j) * 129 + 128];
    float hr = gh[j], hz = gh[H_ + j], hn = gh[2 * H_ + j];
    float r = sigmoidf_(ir + hr);
    float z = sigmoidf_(iz + hz);
    float nn = tanhf(in_ + r * hn);
    float hp = h[idx];
    h[idx] = (1.f - z) * nn + z * hp;
}

__global__ void count_deg(const int* __restrict__ src, float* __restrict__ deg)
{
    int e = blockIdx.x * blockDim.x + threadIdx.x;
    if (e < E_) atomicAdd(&deg[src[e]], 1.0f);
}

// NS[src[e],:] += hu[dst[e],:]
__global__ void scatter_edges(const float* __restrict__ hu,
                              const int* __restrict__ src,
                              const int* __restrict__ dst,
                              float* __restrict__ NS)
{
    int idx = blockIdx.x * blockDim.x + threadIdx.x;   // E_*H_ exact
    int e = idx >> 7, j = idx & 127;
    atomicAdd(&NS[(size_t)src[e] * H_ + j], hu[(size_t)dst[e] * H_ + j]);
}

// h_new = relu(S + [deg>0](NM/deg + bn)); hu<-h_new; logits[n] = h_new . Wc + bc
__global__ void finalize_step(const float* __restrict__ S,
                              const float* __restrict__ NM,
                              const float* __restrict__ deg,
                              const float* __restrict__ bn,
                              const float* __restrict__ Wc,
                              const float* __restrict__ bc,
                              float* __restrict__ hu,
                              float* __restrict__ logits)
{
    int n = blockIdx.x;
    int j = threadIdx.x;   // 128 threads
    float d = deg[n];
    float v = S[(size_t)n * H_ + j];
    if (d > 0.f) v += NM[(size_t)n * H_ + j] / d + bn[j];
    v = fmaxf(v, 0.f);
    hu[(size_t)n * H_ + j] = v;

    float p = v * Wc[j];
#pragma unroll
    for (int o = 16; o > 0; o >>= 1) p += __shfl_xor_sync(0xffffffffu, p, o);
    __shared__ float ws[4];
    if ((j & 31) == 0) ws[j >> 5] = p;
    __syncthreads();
    if (j == 0) logits[n] = ws[0] + ws[1] + ws[2] + ws[3] + bc[0];
}

// ---------------- launch ----------------
extern "C" void kernel_launch(void* const* d_in, const int* in_sizes, int n_in,
                              void* d_out, int out_size)
{
    const float* comments = (const float*)d_in[0];
    const float* truth    = (const float*)d_in[1];
    const int*   esrc     = (const int*)d_in[2];
    const int*   edst     = (const int*)d_in[3];
    const float* Wih_c = (const float*)d_in[4];
    const float* Whh_c = (const float*)d_in[5];
    const float* bih_c = (const float*)d_in[6];
    const float* bhh_c = (const float*)d_in[7];
    const float* Wih_u = (const float*)d_in[8];
    const float* Whh_u = (const float*)d_in[9];
    const float* bih_u = (const float*)d_in[10];
    const float* bhh_u = (const float*)d_in[11];
    const float* Ws_   = (const float*)d_in[12];
    const float* bs_   = (const float*)d_in[13];
    const float* Wn_   = (const float*)d_in[14];
    const float* bn_   = (const float*)d_in[15];
    const float* Wc_   = (const float*)d_in[16];
    const float* bc_   = (const float*)d_in[17];
    float* out = (float*)d_out;

    float *Hc, *Gi, *Gh, *hu, *S, *NS, *NM, *deg;
    cudaGetSymbolAddress((void**)&Hc,  g_Hc);
    cudaGetSymbolAddress((void**)&Gi,  g_Gi);
    cudaGetSymbolAddress((void**)&Gh,  g_Gh);
    cudaGetSymbolAddress((void**)&hu,  g_hu);
    cudaGetSymbolAddress((void**)&S,   g_S);
    cudaGetSymbolAddress((void**)&NS,  g_NS);
    cudaGetSymbolAddress((void**)&NM,  g_NM);
    cudaGetSymbolAddress((void**)&deg, g_deg);

    // ---- phase 1: comment encoder GRU over C steps, batch B_ = T*N ----
    zero_f<<<(B_ * H_ + 255) / 256, 256>>>(Hc, B_ * H_);
    {
        dim3 g1(G_ / BN, B_ / BM);   // (3, 512)
        for (int c = 0; c < C_; c++) {
            // gi = x_c @ Wih_c^T + bih_c   (A = strided view into comments)
            sgemm_nt<<<g1, 256>>>(comments + (size_t)c * D_, C_ * D_,
                                  Wih_c, D_, bih_c, Gi, G_, D_);
            // gh = h @ Whh_c^T + bhh_c
            sgemm_nt<<<g1, 256>>>(Hc, H_, Whh_c, H_, bhh_c, Gh, G_, H_);
            gru_update<<<(B_ * H_ + 255) / 256, 256>>>(Hc, Gi, Gh, B_);
        }
    }

    // ---- graph degree (once) ----
    zero_f<<<(N_ + 255) / 256, 256>>>(deg, N_);
    count_deg<<<E_ / 256, 256>>>(esrc, deg);

    // ---- phase 2: user temporal GRU + GraphSAGE, T steps ----
    zero_f<<<(N_ * H_ + 255) / 256, 256>>>(hu, N_ * H_);
    {
        dim3 g2(G_ / BN, N_ / BM);   // (3, 32)
        dim3 g3(H_ / BN, N_ / BM);   // (1, 32)
        for (int t = 0; t < T_; t++) {
            // gi_u = h_c[t] @ Wih_u[:, :128]^T + bih_u   (ldw = 129)
            sgemm_nt<<<g2, 256>>>(Hc + (size_t)t * N_ * H_, H_,
                                  Wih_u, H_ + 1, bih_u, Gi, G_, H_);
            // gh_u = h @ Whh_u^T + bhh_u
            sgemm_nt<<<g2, 256>>>(hu, H_, Whh_u, H_, bhh_u, Gh, G_, H_);
            gru_update_u<<<(N_ * H_ + 255) / 256, 256>>>(hu, Gi, Gh, Wih_u, truth, t);

            // self message
            sgemm_nt<<<g3, 256>>>(hu, H_, Ws_, H_, bs_, S, H_, H_);
            // neighbor sum (scatter) and linear
            zero_f<<<(N_ * H_ + 255) / 256, 256>>>(NS, N_ * H_);
            scatter_edges<<<(E_ * H_) / 256, 256>>>(hu, esrc, edst, NS);
            sgemm_nt<<<g3, 256>>>(NS, H_, Wn_, H_, nullptr, NM, H_, H_);

            finalize_step<<<N_, H_>>>(S, NM, deg, bn_, Wc_, bc_, hu,
                                      out + (size_t)t * N_);
        }
    }

    // second output of the reference tuple: truth_flags passthrough
    if (out_size >= 2 * T_ * N_) {
        cudaMemcpyAsync(out + (size_t)T_ * N_, truth,
                        sizeof(float) * T_ * N_, cudaMemcpyDeviceToDevice, 0);
    }
    (void)in_sizes; (void)n_in;
}

// round 3
// speedup vs baseline: 1.5667x; 1.5667x over previous
#include <cuda_runtime.h>
#include <cstddef>
#include <math.h>

// ---------------- problem constants ----------------
#define T_ 16
#define N_ 4096
#define C_ 8
#define E_ 65536
#define D_ 256
#define H_ 128
#define G_ 384          // 3*H
#define B_ (T_ * N_)    // 65536

// ---------------- scratch (device globals; no allocation allowed) ----------------
__device__ float g_Hc[B_ * H_];   // comment-GRU hidden, then h_c[t,n,:]
__device__ float g_Gi[B_ * G_];   // gi gate buffer (reused in phase 2 with M=N_)
__device__ float g_Gh[B_ * G_];   // gh gate buffer
__device__ float g_hu[N_ * H_];   // user temporal hidden / h_new carry
__device__ float g_S [N_ * H_];   // self message
__device__ float g_NS[N_ * H_];   // neighbor sum
__device__ float g_NM[N_ * H_];   // neigh_sum @ Wn^T
__device__ float g_deg[N_];       // out-degree (as float)

// ---------------- generic NT SGEMM: C[M,N] = bias[n] + A[M,K] @ W[N,K]^T ----------------
// A row-major with leading dim lda (must be mult of 4, 16B-aligned rows).
// W row-major with leading dim ldw (any stride; scalar loads).
// M % 128 == 0, N % 128 == 0, K % 16 == 0 (guaranteed by the call sites).
#define BM 128
#define BN 128
#define BK 16

__global__ __launch_bounds__(256) void sgemm_nt(
    const float* __restrict__ A, int lda,
    const float* __restrict__ W, int ldw,
    const float* __restrict__ bias,
    float* __restrict__ Cm, int ldc, int K)
{
    __shared__ __align__(16) float As[BK][BM + 4];
    __shared__ __align__(16) float Bs[BK][BN + 4];

    const int tid = threadIdx.x;
    const int tx = tid & 15;        // column group
    const int ty = tid >> 4;        // row group
    const int m0 = blockIdx.y * BM;
    const int n0 = blockIdx.x * BN;

    float acc[8][8];
#pragma unroll
    for (int i = 0; i < 8; i++)
#pragma unroll
        for (int j = 0; j < 8; j++) acc[i][j] = 0.f;

    for (int k0 = 0; k0 < K; k0 += BK) {
        // load A tile (vectorized, lda mult of 4 guarantees alignment)
#pragma unroll
        for (int r = 0; r < 2; r++) {
            int f = tid + r * 256;
            int m = f >> 2;
            int kq = (f & 3) << 2;
            const float4 v = *reinterpret_cast<const float4*>(
                A + (size_t)(m0 + m) * lda + k0 + kq);
            As[kq + 0][m] = v.x; As[kq + 1][m] = v.y;
            As[kq + 2][m] = v.z; As[kq + 3][m] = v.w;
        }
        // load W tile (scalar: ldw may be 129)
#pragma unroll
        for (int r = 0; r < 2; r++) {
            int f = tid + r * 256;
            int n = f >> 2;
            int kq = (f & 3) << 2;
            const float* p = W + (size_t)(n0 + n) * ldw + k0 + kq;
            Bs[kq + 0][n] = p[0]; Bs[kq + 1][n] = p[1];
            Bs[kq + 2][n] = p[2]; Bs[kq + 3][n] = p[3];
        }
        __syncthreads();

#pragma unroll
        for (int k = 0; k < BK; k++) {
            float a[8], b[8];
            *reinterpret_cast<float4*>(&a[0]) = *reinterpret_cast<const float4*>(&As[k][ty * 8]);
            *reinterpret_cast<float4*>(&a[4]) = *reinterpret_cast<const float4*>(&As[k][ty * 8 + 4]);
            *reinterpret_cast<float4*>(&b[0]) = *reinterpret_cast<const float4*>(&Bs[k][tx * 8]);
            *reinterpret_cast<float4*>(&b[4]) = *reinterpret_cast<const float4*>(&Bs[k][tx * 8 + 4]);
#pragma unroll
            for (int i = 0; i < 8; i++)
#pragma unroll
                for (int j = 0; j < 8; j++)
                    acc[i][j] = fmaf(a[i], b[j], acc[i][j]);
        }
        __syncthreads();
    }

    // epilogue
#pragma unroll
    for (int i = 0; i < 8; i++) {
        const int m = m0 + ty * 8 + i;
#pragma unroll
        for (int j = 0; j < 8; j += 4) {
            const int n = n0 + tx * 8 + j;
            float4 o;
            o.x = acc[i][j + 0]; o.y = acc[i][j + 1];
            o.z = acc[i][j + 2]; o.w = acc[i][j + 3];
            if (bias) {
                o.x += bias[n + 0]; o.y += bias[n + 1];
                o.z += bias[n + 2]; o.w += bias[n + 3];
            }
            *reinterpret_cast<float4*>(Cm + (size_t)m * ldc + n) = o;
        }
    }
}

// ---------------- elementwise kernels ----------------
__device__ __forceinline__ float sigmoidf_(float x) { return 1.f / (1.f + expf(-x)); }

__global__ void zero_f(float* __restrict__ p, int n)
{
    int i = blockIdx.x * blockDim.x + threadIdx.x;
    if (i < n) p[i] = 0.f;
}

// h[b,:] <- GRU(h, gi, gh)   (phase 1, in place)
__global__ void gru_update(float* __restrict__ h,
                           const float* __restrict__ Gi,
                           const float* __restrict__ Gh, int Bn)
{
    int idx = blockIdx.x * blockDim.x + threadIdx.x;
    if (idx >= Bn * H_) return;
    int b = idx >> 7, j = idx & 127;
    const float* gi = Gi + (size_t)b * G_;
    const float* gh = Gh + (size_t)b * G_;
    float ir = gi[j], iz = gi[H_ + j], in_ = gi[2 * H_ + j];
    float hr = gh[j], hz = gh[H_ + j], hn = gh[2 * H_ + j];
    float r = sigmoidf_(ir + hr);
    float z = sigmoidf_(iz + hz);
    float nn = tanhf(in_ + r * hn);
    float hp = h[idx];
    h[idx] = (1.f - z) * nn + z * hp;
}

// phase-2 GRU with the prev_y (129th input column) folded in
__global__ void gru_update_u(float* __restrict__ h,
                             const float* __restrict__ Gi,
                             const float* __restrict__ Gh,
                             const float* __restrict__ WihU,   // [384,129]
                             const float* __restrict__ truth, int t)
{
    int idx = blockIdx.x * blockDim.x + threadIdx.x;
    if (idx >= N_ * H_) return;
    int n = idx >> 7, j = idx & 127;
    float py = (t == 0) ? 0.f : truth[(size_t)(t - 1) * N_ + n];
    const float* gi = Gi + (size_t)n * G_;
    const float* gh = Gh + (size_t)n * G_;
    float ir = gi[j]          + py * WihU[(size_t)(j) * 129 + 128];
    float iz = gi[H_ + j]     + py * WihU[(size_t)(H_ + j) * 129 + 128];
    float in_ = gi[2 * H_ + j] + py * WihU[(size_t)(2 * H_ + j) * 129 + 128];
    float hr = gh[j], hz = gh[H_ + j], hn = gh[2 * H_ + j];
    float r = sigmoidf_(ir + hr);
    float z = sigmoidf_(iz + hz);
    float nn = tanhf(in_ + r * hn);
    float hp = h[idx];
    h[idx] = (1.f - z) * nn + z * hp;
}

__global__ void count_deg(const int* __restrict__ src, float* __restrict__ deg)
{
    int e = blockIdx.x * blockDim.x + threadIdx.x;
    if (e < E_) atomicAdd(&deg[src[e]], 1.0f);
}

// NS[src[e],:] += hu[dst[e],:]
__global__ void scatter_edges(const float* __restrict__ hu,
                              const int* __restrict__ src,
                              const int* __restrict__ dst,
                              float* __restrict__ NS)
{
    int idx = blockIdx.x * blockDim.x + threadIdx.x;   // E_*H_ exact
    int e = idx >> 7, j = idx & 127;
    atomicAdd(&NS[(size_t)src[e] * H_ + j], hu[(size_t)dst[e] * H_ + j]);
}

// h_new = relu(S + [deg>0](NM/deg + bn)); hu<-h_new; logits[n] = h_new . Wc + bc
__global__ void finalize_step(const float* __restrict__ S,
                              const float* __restrict__ NM,
                              const float* __restrict__ deg,
                              const float* __restrict__ bn,
                              const float* __restrict__ Wc,
                              const float* __restrict__ bc,
                              float* __restrict__ hu,
                              float* __restrict__ logits)
{
    int n = blockIdx.x;
    int j = threadIdx.x;   // 128 threads
    float d = deg[n];
    float v = S[(size_t)n * H_ + j];
    if (d > 0.f) v += NM[(size_t)n * H_ + j] / d + bn[j];
    v = fmaxf(v, 0.f);
    hu[(size_t)n * H_ + j] = v;

    float p = v * Wc[j];
#pragma unroll
    for (int o = 16; o > 0; o >>= 1) p += __shfl_xor_sync(0xffffffffu, p, o);
    __shared__ float ws[4];
    if ((j & 31) == 0) ws[j >> 5] = p;
    __syncthreads();
    if (j == 0) logits[n] = ws[0] + ws[1] + ws[2] + ws[3] + bc[0];
}

// ---------------- launch ----------------
extern "C" void kernel_launch(void* const* d_in, const int* in_sizes, int n_in,
                              void* d_out, int out_size)
{
    const float* comments = (const float*)d_in[0];
    const float* truth    = (const float*)d_in[1];
    const int*   esrc     = (const int*)d_in[2];
    const int*   edst     = (const int*)d_in[3];
    const float* Wih_c = (const float*)d_in[4];
    const float* Whh_c = (const float*)d_in[5];
    const float* bih_c = (const float*)d_in[6];
    const float* bhh_c = (const float*)d_in[7];
    const float* Wih_u = (const float*)d_in[8];
    const float* Whh_u = (const float*)d_in[9];
    const float* bih_u = (const float*)d_in[10];
    const float* bhh_u = (const float*)d_in[11];
    const float* Ws_   = (const float*)d_in[12];
    const float* bs_   = (const float*)d_in[13];
    const float* Wn_   = (const float*)d_in[14];
    const float* bn_   = (const float*)d_in[15];
    const float* Wc_   = (const float*)d_in[16];
    const float* bc_   = (const float*)d_in[17];
    float* out = (float*)d_out;

    float *Hc, *Gi, *Gh, *hu, *S, *NS, *NM, *deg;
    cudaGetSymbolAddress((void**)&Hc,  g_Hc);
    cudaGetSymbolAddress((void**)&Gi,  g_Gi);
    cudaGetSymbolAddress((void**)&Gh,  g_Gh);
    cudaGetSymbolAddress((void**)&hu,  g_hu);
    cudaGetSymbolAddress((void**)&S,   g_S);
    cudaGetSymbolAddress((void**)&NS,  g_NS);
    cudaGetSymbolAddress((void**)&NM,  g_NM);
    cudaGetSymbolAddress((void**)&deg, g_deg);

    // ---- phase 1: comment encoder GRU over C steps, batch B_ = T*N ----
    zero_f<<<(B_ * H_ + 255) / 256, 256>>>(Hc, B_ * H_);
    {
        dim3 g1(G_ / BN, B_ / BM);   // (3, 512)
        for (int c = 0; c < C_; c++) {
            // gi = x_c @ Wih_c^T + bih_c   (A = strided view into comments)
            sgemm_nt<<<g1, 256>>>(comments + (size_t)c * D_, C_ * D_,
                                  Wih_c, D_, bih_c, Gi, G_, D_);
            // gh = h @ Whh_c^T + bhh_c
            sgemm_nt<<<g1, 256>>>(Hc, H_, Whh_c, H_, bhh_c, Gh, G_, H_);
            gru_update<<<(B_ * H_ + 255) / 256, 256>>>(Hc, Gi, Gh, B_);
        }
    }

    // ---- graph degree (once) ----
    zero_f<<<(N_ + 255) / 256, 256>>>(deg, N_);
    count_deg<<<E_ / 256, 256>>>(esrc, deg);

    // ---- phase 2: user temporal GRU + GraphSAGE, T steps ----
    zero_f<<<(N_ * H_ + 255) / 256, 256>>>(hu, N_ * H_);
    {
        dim3 g2(G_ / BN, N_ / BM);   // (3, 32)
        dim3 g3(H_ / BN, N_ / BM);   // (1, 32)
        for (int t = 0; t < T_; t++) {
            // gi_u = h_c[t] @ Wih_u[:, :128]^T + bih_u   (ldw = 129)
            sgemm_nt<<<g2, 256>>>(Hc + (size_t)t * N_ * H_, H_,
                                  Wih_u, H_ + 1, bih_u, Gi, G_, H_);
            // gh_u = h @ Whh_u^T + bhh_u
            sgemm_nt<<<g2, 256>>>(hu, H_, Whh_u, H_, bhh_u, Gh, G_, H_);
            gru_update_u<<<(N_ * H_ + 255) / 256, 256>>>(hu, Gi, Gh, Wih_u, truth, t);

            // self message
            sgemm_nt<<<g3, 256>>>(hu, H_, Ws_, H_, bs_, S, H_, H_);
            // neighbor sum (scatter) and linear
            zero_f<<<(N_ * H_ + 255) / 256, 256>>>(NS, N_ * H_);
            scatter_edges<<<(E_ * H_) / 256, 256>>>(hu, esrc, edst, NS);
            sgemm_nt<<<g3, 256>>>(NS, H_, Wn_, H_, nullptr, NM, H_, H_);

            finalize_step<<<N_, H_>>>(S, NM, deg, bn_, Wc_, bc_, hu,
                                      out + (size_t)t * N_);
        }
    }

    // second output of the reference tuple: truth_flags passthrough
    if (out_size >= 2 * T_ * N_) {
        cudaMemcpyAsync(out + (size_t)T_ * N_, truth,
                        sizeof(float) * T_ * N_, cudaMemcpyDeviceToDevice, 0);
    }
    (void)in_sizes; (void)n_in;
}